// round 14
// baseline (speedup 1.0000x reference)
#include <cuda_runtime.h>
#include <cuda_fp16.h>
#include <cstdint>

#define NPATH 15
#define NENT 33

__constant__ int c_l1[NPATH] = {0,0,0,1,1,1,1,1,1,2,2,2,2,2,2};
__constant__ int c_l2[NPATH] = {0,1,2,0,1,1,1,2,2,0,1,1,2,2,2};
__constant__ int c_lo[NPATH] = {0,1,2,1,0,1,2,1,2,2,1,2,0,1,2};

// schedule: 5 passes over ko slots {0,1},{2,3},{4,5},{6,7},{8}
__constant__ int S_path[NENT] = {0,4,12,1,3,5,7,10,13, 1,3,5,7,10,13, 2,6,8,9,11,14, 2,6,8,9,11,14, 2,6,8,9,11,14};
__constant__ int S_k0[NENT]   = {0,0,0, 0,0,0,0,0,0,   1,1,1,1,1,1,   0,0,0,0,0,0,   2,2,2,2,2,2,   4,4,4,4,4,4};
__constant__ int S_nk[NENT]   = {1,1,1, 1,1,1,1,1,1,   2,2,2,2,2,2,   2,2,2,2,2,2,   2,2,2,2,2,2,   1,1,1,1,1,1};
__constant__ int S_slot[NENT] = {0,0,0, 1,1,1,1,1,1,   0,0,0,0,0,0,   0,0,0,0,0,0,   0,0,0,0,0,0,   0,0,0,0,0,0};
__constant__ int P_end[5] = {9,15,21,27,33};
__constant__ int P_kob[5] = {0,2,4,6,8};
__constant__ int P_ns[5]  = {2,2,2,2,1};

__device__ float g_w3j[NPATH * 125];
__device__ __half g_Wh[NPATH * 16384];   // fp16, swizzled [u-row 256B]

// smem layout (dynamic), 64-sample tile, single-fp16 A (16KB per slot)
#define SO_X2 0
#define SO_SC 2304
#define SO_WH 8192
#define SO_A0 40960
#define SO_A1 57344
#define SMEM_BYTES 73728

#define THREADS 256
#define TILE_Z 64

// ---------------- merged setup ----------------
__device__ __forceinline__ void qentry(int l, int r, int c, float& re, float& im) {
    int m = r - l;
    const float s2 = 0.70710678118654752440f;
    float a = 0.0f, b = 0.0f;
    if (m < 0) {
        if (c == l - m)      a = s2;
        else if (c == l + m) b = -s2;
    } else if (m == 0) {
        if (c == l) a = 1.0f;
    } else {
        float sg = (m & 1) ? -1.0f : 1.0f;
        if (c == l + m)      a = sg * s2;
        else if (c == l - m) b = sg * s2;
    }
    switch (l & 3) {
        case 0: re = a;  im = b;  break;
        case 1: re = b;  im = -a; break;
        case 2: re = -a; im = -b; break;
        default: re = -b; im = a; break;
    }
}

__device__ float su2_cg(int j1, int m1, int j2, int m2, int j3, int m3) {
    if (m3 != m1 + m2) return 0.0f;
    const float F[8] = {1.0f, 1.0f, 2.0f, 6.0f, 24.0f, 120.0f, 720.0f, 5040.0f};
    int vmin = -j1 + j2 + m3; if (-j1 + m1 > vmin) vmin = -j1 + m1; if (vmin < 0) vmin = 0;
    int vmax = j2 + j3 + m1; if (j3 - j1 + j2 < vmax) vmax = j3 - j1 + j2; if (j3 + m3 < vmax) vmax = j3 + m3;
    float C = sqrtf((2.0f * j3 + 1.0f)
                    * F[j3 + j1 - j2] * F[j3 - j1 + j2] * F[j1 + j2 - j3] / F[j1 + j2 + j3 + 1]
                    * F[j3 + m3] * F[j3 - m3]
                    / (F[j1 - m1] * F[j1 + m1] * F[j2 - m2] * F[j2 + m2]));
    float S = 0.0f;
    for (int v = vmin; v <= vmax; v++) {
        float sgn = ((v + j2 + m2) & 1) ? -1.0f : 1.0f;
        S += sgn / F[v] * F[j2 + j3 + m1 - v] * F[j1 - m1 + v]
             / (F[j3 - j1 + j2 - v] * F[j3 + m3 - v] * F[v + j1 - j2 - m3]);
    }
    return C * S;
}

__global__ void setup_kernel(const float* __restrict__ wt) {
    __shared__ float red[128];
    int blk = blockIdx.x;
    int tid = threadIdx.x;

    if (blk < 120) {
        int p = blk >> 3;
        int seg = blk & 7;
        // ---- Wh: fp16 + swizzle (row u = 256B, granule XOR) ----
        int base = seg * 2048;
        for (int q = tid; q < 2048; q += 256) {
            int idx = base + q;
            int u = idx >> 7, w = idx & 127;
            float v = wt[p * 16384 + idx];
            uint32_t off = (uint32_t)(u * 256 + (((w >> 3) ^ (u & 7)) << 4) + (w & 7) * 2);
            *(__half*)((char*)g_Wh + p * 32768 + off) = __float2half_rn(v);
        }
        return;
    }

    // ---- w3j (fp32, validated) ----
    int p = blk - 120;
    int l1 = c_l1[p], l2 = c_l2[p], l3 = c_lo[p];
    int n1 = 2 * l1 + 1, n2 = 2 * l2 + 1, n3 = 2 * l3 + 1;
    int a = tid / 25, b = (tid / 5) % 5, cc = tid % 5;

    float val = 0.0f;
    if (tid < 125 && a < n1 && b < n2 && cc < n3) {
        for (int i = 0; i < n1; i++) {
            float q1r, q1i; qentry(l1, i, a, q1r, q1i);
            if (q1r == 0.0f && q1i == 0.0f) continue;
            for (int k = 0; k < n2; k++) {
                float q2r, q2i; qentry(l2, k, b, q2r, q2i);
                if (q2r == 0.0f && q2i == 0.0f) continue;
                float pr = q1r * q2r - q1i * q2i;
                float pi = q1r * q2i + q1i * q2r;
                for (int nn = 0; nn < n3; nn++) {
                    float q3r, q3i; qentry(l3, nn, cc, q3r, q3i);
                    if (q3r == 0.0f && q3i == 0.0f) continue;
                    float cg = su2_cg(l1, i - l1, l2, k - l2, l3, nn - l3);
                    if (cg == 0.0f) continue;
                    val += cg * (pr * q3r + pi * q3i);
                }
            }
        }
    }

    if (tid < 128) red[tid] = val * val;
    __syncthreads();
    for (int s = 64; s > 0; s >>= 1) {
        if (tid < s && tid + s < 128) red[tid] += red[tid + s];
        __syncthreads();
    }
    float norm = sqrtf(red[0]);
    const int iocnt[3] = {3, 6, 6};
    float alpha = sqrtf((float)(2 * l3 + 1) / (128.0f * (float)iocnt[l3]));
    float outv = 0.0f;
    if (norm > 0.0f) outv = val / norm * alpha;
    if (tid < 125) g_w3j[p * 125 + tid] = outv;
}

// ---------------- mma helpers ----------------
__device__ __forceinline__ uint32_t smem_u32(const void* p) {
    uint32_t a;
    asm("{ .reg .u64 t; cvta.to.shared.u64 t, %1; cvt.u32.u64 %0, t; }" : "=r"(a) : "l"(p));
    return a;
}
__device__ __forceinline__ void cp_async16(uint32_t dst, const void* src) {
    asm volatile("cp.async.cg.shared.global [%0], [%1], 16;" :: "r"(dst), "l"(src));
}
__device__ __forceinline__ void ldsm_x4(uint32_t* r, uint32_t a) {
    asm volatile("ldmatrix.sync.aligned.m8n8.x4.shared.b16 {%0,%1,%2,%3}, [%4];"
                 : "=r"(r[0]), "=r"(r[1]), "=r"(r[2]), "=r"(r[3]) : "r"(a));
}
__device__ __forceinline__ void ldsm_x4t(uint32_t* r, uint32_t a) {
    asm volatile("ldmatrix.sync.aligned.m8n8.x4.trans.shared.b16 {%0,%1,%2,%3}, [%4];"
                 : "=r"(r[0]), "=r"(r[1]), "=r"(r[2]), "=r"(r[3]) : "r"(a));
}
__device__ __forceinline__ void mma16816(float (&d)[4], const uint32_t* a, const uint32_t* b) {
    asm volatile("mma.sync.aligned.m16n8k16.row.col.f32.f16.f16.f32 "
                 "{%0,%1,%2,%3}, {%4,%5,%6,%7}, {%8,%9}, {%0,%1,%2,%3};"
                 : "+f"(d[0]), "+f"(d[1]), "+f"(d[2]), "+f"(d[3])
                 : "r"(a[0]), "r"(a[1]), "r"(a[2]), "r"(a[3]), "r"(b[0]), "r"(b[1]));
}

// Warp tile: 16 z-rows x 64 w-cols. A rows 64, row stride 256B.
// 1-product scheme: D = A16 * W16.
__device__ __forceinline__ void mma_phase(uint32_t Ab, uint32_t Wb,
                                          float (&acc)[8][4], int lane,
                                          int zrow0, int nh) {
    const int m = lane >> 3, r = lane & 7;
#pragma unroll
    for (int kk = 0; kk < 8; kk++) {
        uint32_t ah[4];
        const int gc = kk * 2 + (m >> 1);
        const int row = zrow0 + r + (m & 1) * 8;
        uint32_t aaddr = Ab + (uint32_t)(row * 256 + ((gc ^ (row & 7)) << 4));
        ldsm_x4(ah, aaddr);
        const int krow = kk * 16 + ((m & 1) << 3) + r;
        const int swr = krow & 7;
        const uint32_t brow_base = Wb + (uint32_t)(krow * 256);
#pragma unroll
        for (int ntp = 0; ntp < 4; ntp++) {
            int ntg = nh * 8 + ntp * 2 + (m >> 1);
            uint32_t baddr = brow_base + (uint32_t)((ntg ^ swr) << 4);
            uint32_t bh[4];
            ldsm_x4t(bh, baddr);
#pragma unroll
            for (int q = 0; q < 2; q++)
                mma16816(acc[ntp * 2 + q], ah, bh + q * 2);
        }
    }
}

__device__ __forceinline__ void store_acc(float (&acc)[8][4], float* __restrict__ out,
                                          int ko, int z0, int zrow0, int nh,
                                          int lane, int n) {
    const int col0 = nh * 64 + (lane & 3) * 2;
    const int r0 = z0 + zrow0 + (lane >> 2);
#pragma unroll
    for (int nt = 0; nt < 8; nt++) {
        if (r0 < n)
            *(float2*)(out + (long)r0 * 1152 + ko * 128 + col0 + nt * 8) =
                make_float2(acc[nt][0], acc[nt][1]);
        if (r0 + 8 < n)
            *(float2*)(out + (long)(r0 + 8) * 1152 + ko * 128 + col0 + nt * 8) =
                make_float2(acc[nt][2], acc[nt][3]);
        acc[nt][0] = acc[nt][1] = acc[nt][2] = acc[nt][3] = 0.0f;
    }
}

// ---------------- templated A-tile build (64 z x 128 u, single fp16) ----------------
template<int N1, int NK>
__device__ __forceinline__ void build_A(char* smem, const float* __restrict__ x1,
                                        const float* __restrict__ sC, long z0,
                                        int s1, int n, bool full) {
    const int t = threadIdx.x;
#pragma unroll 4
    for (int it = 0; it < 16; it++) {
        int idx = t + it * THREADS;
        int z = idx >> 6, u2 = idx & 63;
        long zg = z0 + z;
        float2 xv[N1];
        const float* xr = x1 + zg * 1152 + s1 * 128 + u2 * 2;
        if (full || zg < n) {
#pragma unroll
            for (int i = 0; i < N1; i++) xv[i] = *(const float2*)(xr + i * 128);
        } else {
#pragma unroll
            for (int i = 0; i < N1; i++) { xv[i].x = 0.0f; xv[i].y = 0.0f; }
        }
        uint32_t boff = (uint32_t)(z * 256 + (((u2 >> 2) ^ (z & 7)) << 4) + (u2 & 3) * 4);
#pragma unroll
        for (int kq = 0; kq < NK; kq++) {
            float a0 = 0.0f, a1 = 0.0f;
#pragma unroll
            for (int i = 0; i < N1; i++) {
                float c = sC[z * 12 + i * 2 + kq];
                a0 = fmaf(c, xv[i].x, a0);
                a1 = fmaf(c, xv[i].y, a1);
            }
            __half h0 = __float2half_rn(a0);
            __half h1 = __float2half_rn(a1);
            uint32_t hp = ((uint32_t)__half_as_ushort(h1) << 16) | __half_as_ushort(h0);
            *(uint32_t*)(smem + (kq ? SO_A1 : SO_A0) + boff) = hp;
        }
    }
}

// ---------------- main kernel ----------------
__global__ __launch_bounds__(THREADS, 3)
void tp_mma_kernel(const float* __restrict__ x1, const float* __restrict__ x2,
                   float* __restrict__ out, int n) {
    extern __shared__ __align__(1024) char smem[];
    uint32_t sb = smem_u32(smem);
    const int t = threadIdx.x;
    const int wid = t >> 5, lane = t & 31;
    const int z0 = blockIdx.x * TILE_Z;
    const int zrow0 = (wid >> 1) * 16;     // 4 z-tiles of 16
    const int nh = wid & 1;                // warp n-half
    const bool full = (z0 + TILE_Z <= n);

    float* sX2 = (float*)(smem + SO_X2);
    float* sC  = (float*)(smem + SO_SC);

    for (int idx = t; idx < TILE_Z * 9; idx += THREADS) {
        int z = idx / 9, j = idx - z * 9;
        int zg = z0 + z;
        sX2[idx] = (full || zg < n) ? x2[(long)zg * 9 + j] : 0.0f;
    }

    float acc0[8][4], acc1[8][4];
#pragma unroll
    for (int nt = 0; nt < 8; nt++)
#pragma unroll
        for (int j = 0; j < 4; j++) { acc0[nt][j] = 0.0f; acc1[nt][j] = 0.0f; }

    int pass = 0;

    for (int e = 0; e < NENT; e++) {
        const int p = S_path[e], k0 = S_k0[e], nk = S_nk[e], sl = S_slot[e];
        const int l1 = c_l1[p], l2 = c_l2[p];
        const int n1 = 2 * l1 + 1, n2 = 2 * l2 + 1;
        const int s1 = l1 * l1, s2 = l2 * l2;

        __syncthreads();   // prior MMA reads done before overwriting W/A/sC

        // stage Wh via cp.async (overlaps with c + A build below)
        {
            const char* srcH = (const char*)g_Wh + p * 32768;
#pragma unroll
            for (int i = 0; i < 8; i++) {
                int q = (t + i * THREADS) * 16;
                cp_async16(sb + SO_WH + q, srcH + q);
            }
            asm volatile("cp.async.commit_group;" ::: "memory");
        }

        // c[z][i][kq]
        if (t < TILE_Z) {
            for (int i = 0; i < n1; i++)
                for (int kq = 0; kq < nk; kq++) {
                    int k = k0 + kq;
                    float s = 0.0f;
                    for (int j = 0; j < n2; j++)
                        s += g_w3j[p * 125 + (i * 5 + j) * 5 + k] * sX2[t * 9 + s2 + j];
                    sC[t * 12 + i * 2 + kq] = s;
                }
        }
        __syncthreads();

        // build A tiles (single fp16, swizzled)
        if (nk == 1) {
            if (n1 == 1)      build_A<1,1>(smem, x1, sC, z0, s1, n, full);
            else if (n1 == 3) build_A<3,1>(smem, x1, sC, z0, s1, n, full);
            else              build_A<5,1>(smem, x1, sC, z0, s1, n, full);
        } else {
            if (n1 == 1)      build_A<1,2>(smem, x1, sC, z0, s1, n, full);
            else if (n1 == 3) build_A<3,2>(smem, x1, sC, z0, s1, n, full);
            else              build_A<5,2>(smem, x1, sC, z0, s1, n, full);
        }
        asm volatile("cp.async.wait_group 0;" ::: "memory");
        __syncthreads();

        // MMA (single product A16*W16)
        uint32_t Wb = sb + SO_WH;
        if (nk == 1) {
            if (sl == 0) mma_phase(sb + SO_A0, Wb, acc0, lane, zrow0, nh);
            else         mma_phase(sb + SO_A0, Wb, acc1, lane, zrow0, nh);
        } else {
            mma_phase(sb + SO_A0, Wb, acc0, lane, zrow0, nh);
            mma_phase(sb + SO_A1, Wb, acc1, lane, zrow0, nh);
        }

        // pass epilogue
        if (e == P_end[pass] - 1) {
            int kob = P_kob[pass], ns = P_ns[pass];
            store_acc(acc0, out, kob, z0, zrow0, nh, lane, n);
            if (ns == 2) store_acc(acc1, out, kob + 1, z0, zrow0, nh, lane, n);
            pass++;
        }
    }
}

// ---------------------------------------------------------------------------

extern "C" void kernel_launch(void* const* d_in, const int* in_sizes, int n_in,
                              void* d_out, int out_size) {
    const float* x1 = (const float*)d_in[0];   // (N, 9, 128)
    const float* x2 = (const float*)d_in[1];   // (N, 9, 1)
    const float* wt = (const float*)d_in[2];   // (15*128*128,)
    float* out = (float*)d_out;                // (N, 9, 128)

    int n = in_sizes[0] / 1152;

    setup_kernel<<<135, 256>>>(wt);

    cudaFuncSetAttribute(tp_mma_kernel, cudaFuncAttributeMaxDynamicSharedMemorySize, SMEM_BYTES);
    tp_mma_kernel<<<(n + TILE_Z - 1) / TILE_Z, THREADS, SMEM_BYTES>>>(x1, x2, out, n);
}

// round 17
// speedup vs baseline: 1.6294x; 1.6294x over previous
#include <cuda_runtime.h>
#include <cuda_fp16.h>
#include <cstdint>

#define NPATH 15
#define NENT 33

__constant__ int c_l1[NPATH] = {0,0,0,1,1,1,1,1,1,2,2,2,2,2,2};
__constant__ int c_l2[NPATH] = {0,1,2,0,1,1,1,2,2,0,1,1,2,2,2};
__constant__ int c_lo[NPATH] = {0,1,2,1,0,1,2,1,2,2,1,2,0,1,2};

// schedule: 5 passes over ko slots {0,1},{2,3},{4,5},{6,7},{8}
__constant__ int S_path[NENT] = {0,4,12,1,3,5,7,10,13, 1,3,5,7,10,13, 2,6,8,9,11,14, 2,6,8,9,11,14, 2,6,8,9,11,14};
__constant__ int S_k0[NENT]   = {0,0,0, 0,0,0,0,0,0,   1,1,1,1,1,1,   0,0,0,0,0,0,   2,2,2,2,2,2,   4,4,4,4,4,4};
__constant__ int S_nk[NENT]   = {1,1,1, 1,1,1,1,1,1,   2,2,2,2,2,2,   2,2,2,2,2,2,   2,2,2,2,2,2,   1,1,1,1,1,1};
__constant__ int S_slot[NENT] = {0,0,0, 1,1,1,1,1,1,   0,0,0,0,0,0,   0,0,0,0,0,0,   0,0,0,0,0,0,   0,0,0,0,0,0};
__constant__ int P_end[5] = {9,15,21,27,33};
__constant__ int P_kob[5] = {0,2,4,6,8};
__constant__ int P_ns[5]  = {2,2,2,2,1};

__device__ float g_w3j[NPATH * 125];
__device__ __half g_Wh[NPATH * 16384];   // fp16, swizzled [u-row 256B]

// smem layout (dynamic), 64-sample tile, single-fp16 A (16KB per slot)
#define SO_X2 0
#define SO_SC 2304
#define SO_WH 8192
#define SO_A0 40960
#define SO_A1 57344
#define SMEM_BYTES 73728

#define THREADS 256
#define TILE_Z 64

// ---------------- merged setup ----------------
__device__ __forceinline__ void qentry(int l, int r, int c, float& re, float& im) {
    int m = r - l;
    const float s2 = 0.70710678118654752440f;
    float a = 0.0f, b = 0.0f;
    if (m < 0) {
        if (c == l - m)      a = s2;
        else if (c == l + m) b = -s2;
    } else if (m == 0) {
        if (c == l) a = 1.0f;
    } else {
        float sg = (m & 1) ? -1.0f : 1.0f;
        if (c == l + m)      a = sg * s2;
        else if (c == l - m) b = sg * s2;
    }
    switch (l & 3) {
        case 0: re = a;  im = b;  break;
        case 1: re = b;  im = -a; break;
        case 2: re = -a; im = -b; break;
        default: re = -b; im = a; break;
    }
}

__device__ float su2_cg(int j1, int m1, int j2, int m2, int j3, int m3) {
    if (m3 != m1 + m2) return 0.0f;
    const float F[8] = {1.0f, 1.0f, 2.0f, 6.0f, 24.0f, 120.0f, 720.0f, 5040.0f};
    int vmin = -j1 + j2 + m3; if (-j1 + m1 > vmin) vmin = -j1 + m1; if (vmin < 0) vmin = 0;
    int vmax = j2 + j3 + m1; if (j3 - j1 + j2 < vmax) vmax = j3 - j1 + j2; if (j3 + m3 < vmax) vmax = j3 + m3;
    float C = sqrtf((2.0f * j3 + 1.0f)
                    * F[j3 + j1 - j2] * F[j3 - j1 + j2] * F[j1 + j2 - j3] / F[j1 + j2 + j3 + 1]
                    * F[j3 + m3] * F[j3 - m3]
                    / (F[j1 - m1] * F[j1 + m1] * F[j2 - m2] * F[j2 + m2]));
    float S = 0.0f;
    for (int v = vmin; v <= vmax; v++) {
        float sgn = ((v + j2 + m2) & 1) ? -1.0f : 1.0f;
        S += sgn / F[v] * F[j2 + j3 + m1 - v] * F[j1 - m1 + v]
             / (F[j3 - j1 + j2 - v] * F[j3 + m3 - v] * F[v + j1 - j2 - m3]);
    }
    return C * S;
}

__global__ void setup_kernel(const float* __restrict__ wt) {
    __shared__ float red[128];
    int blk = blockIdx.x;
    int tid = threadIdx.x;

    if (blk < 120) {
        int p = blk >> 3;
        int seg = blk & 7;
        // ---- Wh: fp16 + swizzle (row u = 256B, granule XOR) ----
        int base = seg * 2048;
        for (int q = tid; q < 2048; q += 256) {
            int idx = base + q;
            int u = idx >> 7, w = idx & 127;
            float v = wt[p * 16384 + idx];
            uint32_t off = (uint32_t)(u * 256 + (((w >> 3) ^ (u & 7)) << 4) + (w & 7) * 2);
            *(__half*)((char*)g_Wh + p * 32768 + off) = __float2half_rn(v);
        }
        return;
    }

    // ---- w3j (fp32, validated) ----
    int p = blk - 120;
    int l1 = c_l1[p], l2 = c_l2[p], l3 = c_lo[p];
    int n1 = 2 * l1 + 1, n2 = 2 * l2 + 1, n3 = 2 * l3 + 1;
    int a = tid / 25, b = (tid / 5) % 5, cc = tid % 5;

    float val = 0.0f;
    if (tid < 125 && a < n1 && b < n2 && cc < n3) {
        for (int i = 0; i < n1; i++) {
            float q1r, q1i; qentry(l1, i, a, q1r, q1i);
            if (q1r == 0.0f && q1i == 0.0f) continue;
            for (int k = 0; k < n2; k++) {
                float q2r, q2i; qentry(l2, k, b, q2r, q2i);
                if (q2r == 0.0f && q2i == 0.0f) continue;
                float pr = q1r * q2r - q1i * q2i;
                float pi = q1r * q2i + q1i * q2r;
                for (int nn = 0; nn < n3; nn++) {
                    float q3r, q3i; qentry(l3, nn, cc, q3r, q3i);
                    if (q3r == 0.0f && q3i == 0.0f) continue;
                    float cg = su2_cg(l1, i - l1, l2, k - l2, l3, nn - l3);
                    if (cg == 0.0f) continue;
                    val += cg * (pr * q3r + pi * q3i);
                }
            }
        }
    }

    if (tid < 128) red[tid] = val * val;
    __syncthreads();
    for (int s = 64; s > 0; s >>= 1) {
        if (tid < s && tid + s < 128) red[tid] += red[tid + s];
        __syncthreads();
    }
    float norm = sqrtf(red[0]);
    const int iocnt[3] = {3, 6, 6};
    float alpha = sqrtf((float)(2 * l3 + 1) / (128.0f * (float)iocnt[l3]));
    float outv = 0.0f;
    if (norm > 0.0f) outv = val / norm * alpha;
    if (tid < 125) g_w3j[p * 125 + tid] = outv;
}

// ---------------- mma helpers ----------------
__device__ __forceinline__ uint32_t smem_u32(const void* p) {
    uint32_t a;
    asm("{ .reg .u64 t; cvta.to.shared.u64 t, %1; cvt.u32.u64 %0, t; }" : "=r"(a) : "l"(p));
    return a;
}
__device__ __forceinline__ void cp_async16(uint32_t dst, const void* src) {
    asm volatile("cp.async.cg.shared.global [%0], [%1], 16;" :: "r"(dst), "l"(src));
}
__device__ __forceinline__ void ldsm_x4(uint32_t* r, uint32_t a) {
    asm volatile("ldmatrix.sync.aligned.m8n8.x4.shared.b16 {%0,%1,%2,%3}, [%4];"
                 : "=r"(r[0]), "=r"(r[1]), "=r"(r[2]), "=r"(r[3]) : "r"(a));
}
__device__ __forceinline__ void ldsm_x4t(uint32_t* r, uint32_t a) {
    asm volatile("ldmatrix.sync.aligned.m8n8.x4.trans.shared.b16 {%0,%1,%2,%3}, [%4];"
                 : "=r"(r[0]), "=r"(r[1]), "=r"(r[2]), "=r"(r[3]) : "r"(a));
}
__device__ __forceinline__ void mma16816(float (&d)[4], const uint32_t* a, const uint32_t* b) {
    asm volatile("mma.sync.aligned.m16n8k16.row.col.f32.f16.f16.f32 "
                 "{%0,%1,%2,%3}, {%4,%5,%6,%7}, {%8,%9}, {%0,%1,%2,%3};"
                 : "+f"(d[0]), "+f"(d[1]), "+f"(d[2]), "+f"(d[3])
                 : "r"(a[0]), "r"(a[1]), "r"(a[2]), "r"(a[3]), "r"(b[0]), "r"(b[1]));
}

// Warp tile: 16 z-rows x 64 w-cols. A rows 64, row stride 256B.
// 1-product scheme: D = A16 * W16.
__device__ __forceinline__ void mma_phase(uint32_t Ab, uint32_t Wb,
                                          float (&acc)[8][4], int lane,
                                          int zrow0, int nh) {
    const int m = lane >> 3, r = lane & 7;
#pragma unroll
    for (int kk = 0; kk < 8; kk++) {
        uint32_t ah[4];
        const int gc = kk * 2 + (m >> 1);
        const int row = zrow0 + r + (m & 1) * 8;
        uint32_t aaddr = Ab + (uint32_t)(row * 256 + ((gc ^ (row & 7)) << 4));
        ldsm_x4(ah, aaddr);
        const int krow = kk * 16 + ((m & 1) << 3) + r;
        const int swr = krow & 7;
        const uint32_t brow_base = Wb + (uint32_t)(krow * 256);
#pragma unroll
        for (int ntp = 0; ntp < 4; ntp++) {
            int ntg = nh * 8 + ntp * 2 + (m >> 1);
            uint32_t baddr = brow_base + (uint32_t)((ntg ^ swr) << 4);
            uint32_t bh[4];
            ldsm_x4t(bh, baddr);
#pragma unroll
            for (int q = 0; q < 2; q++)
                mma16816(acc[ntp * 2 + q], ah, bh + q * 2);
        }
    }
}

__device__ __forceinline__ void store_acc(float (&acc)[8][4], float* __restrict__ out,
                                          int ko, int z0, int zrow0, int nh,
                                          int lane, int n) {
    const int col0 = nh * 64 + (lane & 3) * 2;
    const int r0 = z0 + zrow0 + (lane >> 2);
#pragma unroll
    for (int nt = 0; nt < 8; nt++) {
        if (r0 < n)
            *(float2*)(out + (long)r0 * 1152 + ko * 128 + col0 + nt * 8) =
                make_float2(acc[nt][0], acc[nt][1]);
        if (r0 + 8 < n)
            *(float2*)(out + (long)(r0 + 8) * 1152 + ko * 128 + col0 + nt * 8) =
                make_float2(acc[nt][2], acc[nt][3]);
        acc[nt][0] = acc[nt][1] = acc[nt][2] = acc[nt][3] = 0.0f;
    }
}

// ---------------- templated A-tile build (64 z x 128 u, single fp16) ----------------
template<int N1, int NK>
__device__ __forceinline__ void build_A(char* smem, const float* __restrict__ x1,
                                        const float* __restrict__ sC, long z0,
                                        int s1, int n, bool full) {
    const int t = threadIdx.x;
#pragma unroll 4
    for (int it = 0; it < 16; it++) {
        int idx = t + it * THREADS;
        int z = idx >> 6, u2 = idx & 63;
        long zg = z0 + z;
        float2 xv[N1];
        const float* xr = x1 + zg * 1152 + s1 * 128 + u2 * 2;
        if (full || zg < n) {
#pragma unroll
            for (int i = 0; i < N1; i++) xv[i] = *(const float2*)(xr + i * 128);
        } else {
#pragma unroll
            for (int i = 0; i < N1; i++) { xv[i].x = 0.0f; xv[i].y = 0.0f; }
        }
        uint32_t boff = (uint32_t)(z * 256 + (((u2 >> 2) ^ (z & 7)) << 4) + (u2 & 3) * 4);
#pragma unroll
        for (int kq = 0; kq < NK; kq++) {
            float a0 = 0.0f, a1 = 0.0f;
#pragma unroll
            for (int i = 0; i < N1; i++) {
                float c = sC[z * 12 + i * 2 + kq];
                a0 = fmaf(c, xv[i].x, a0);
                a1 = fmaf(c, xv[i].y, a1);
            }
            __half h0 = __float2half_rn(a0);
            __half h1 = __float2half_rn(a1);
            uint32_t hp = ((uint32_t)__half_as_ushort(h1) << 16) | __half_as_ushort(h0);
            *(uint32_t*)(smem + (kq ? SO_A1 : SO_A0) + boff) = hp;
        }
    }
}

// ---------------- main kernel ----------------
__global__ __launch_bounds__(THREADS, 2)
void tp_mma_kernel(const float* __restrict__ x1, const float* __restrict__ x2,
                   float* __restrict__ out, int n) {
    extern __shared__ __align__(1024) char smem[];
    uint32_t sb = smem_u32(smem);
    const int t = threadIdx.x;
    const int wid = t >> 5, lane = t & 31;
    const int z0 = blockIdx.x * TILE_Z;
    const int zrow0 = (wid >> 1) * 16;     // 4 z-tiles of 16
    const int nh = wid & 1;                // warp n-half
    const bool full = (z0 + TILE_Z <= n);

    float* sX2 = (float*)(smem + SO_X2);
    float* sC  = (float*)(smem + SO_SC);

    for (int idx = t; idx < TILE_Z * 9; idx += THREADS) {
        int z = idx / 9, j = idx - z * 9;
        int zg = z0 + z;
        sX2[idx] = (full || zg < n) ? x2[(long)zg * 9 + j] : 0.0f;
    }

    float acc0[8][4], acc1[8][4];
#pragma unroll
    for (int nt = 0; nt < 8; nt++)
#pragma unroll
        for (int j = 0; j < 4; j++) { acc0[nt][j] = 0.0f; acc1[nt][j] = 0.0f; }

    int pass = 0;

    for (int e = 0; e < NENT; e++) {
        const int p = S_path[e], k0 = S_k0[e], nk = S_nk[e], sl = S_slot[e];
        const int l1 = c_l1[p], l2 = c_l2[p];
        const int n1 = 2 * l1 + 1, n2 = 2 * l2 + 1;
        const int s1 = l1 * l1, s2 = l2 * l2;

        __syncthreads();   // prior MMA reads done before overwriting W/A/sC

        // stage Wh via cp.async (overlaps with c + A build below)
        {
            const char* srcH = (const char*)g_Wh + p * 32768;
#pragma unroll
            for (int i = 0; i < 8; i++) {
                int q = (t + i * THREADS) * 16;
                cp_async16(sb + SO_WH + q, srcH + q);
            }
            asm volatile("cp.async.commit_group;" ::: "memory");
        }

        // c[z][i][kq]
        if (t < TILE_Z) {
            for (int i = 0; i < n1; i++)
                for (int kq = 0; kq < nk; kq++) {
                    int k = k0 + kq;
                    float s = 0.0f;
                    for (int j = 0; j < n2; j++)
                        s += g_w3j[p * 125 + (i * 5 + j) * 5 + k] * sX2[t * 9 + s2 + j];
                    sC[t * 12 + i * 2 + kq] = s;
                }
        }
        __syncthreads();

        // build A tiles (single fp16, swizzled)
        if (nk == 1) {
            if (n1 == 1)      build_A<1,1>(smem, x1, sC, z0, s1, n, full);
            else if (n1 == 3) build_A<3,1>(smem, x1, sC, z0, s1, n, full);
            else              build_A<5,1>(smem, x1, sC, z0, s1, n, full);
        } else {
            if (n1 == 1)      build_A<1,2>(smem, x1, sC, z0, s1, n, full);
            else if (n1 == 3) build_A<3,2>(smem, x1, sC, z0, s1, n, full);
            else              build_A<5,2>(smem, x1, sC, z0, s1, n, full);
        }
        asm volatile("cp.async.wait_group 0;" ::: "memory");
        __syncthreads();

        // MMA (single product A16*W16)
        uint32_t Wb = sb + SO_WH;
        if (nk == 1) {
            if (sl == 0) mma_phase(sb + SO_A0, Wb, acc0, lane, zrow0, nh);
            else         mma_phase(sb + SO_A0, Wb, acc1, lane, zrow0, nh);
        } else {
            mma_phase(sb + SO_A0, Wb, acc0, lane, zrow0, nh);
            mma_phase(sb + SO_A1, Wb, acc1, lane, zrow0, nh);
        }

        // pass epilogue
        if (e == P_end[pass] - 1) {
            int kob = P_kob[pass], ns = P_ns[pass];
            store_acc(acc0, out, kob, z0, zrow0, nh, lane, n);
            if (ns == 2) store_acc(acc1, out, kob + 1, z0, zrow0, nh, lane, n);
            pass++;
        }
    }
}

// ---------------------------------------------------------------------------

extern "C" void kernel_launch(void* const* d_in, const int* in_sizes, int n_in,
                              void* d_out, int out_size) {
    const float* x1 = (const float*)d_in[0];   // (N, 9, 128)
    const float* x2 = (const float*)d_in[1];   // (N, 9, 1)
    const float* wt = (const float*)d_in[2];   // (15*128*128,)
    float* out = (float*)d_out;                // (N, 9, 128)

    int n = in_sizes[0] / 1152;

    setup_kernel<<<135, 256>>>(wt);

    cudaFuncSetAttribute(tp_mma_kernel, cudaFuncAttributeMaxDynamicSharedMemorySize, SMEM_BYTES);
    tp_mma_kernel<<<(n + TILE_Z - 1) / TILE_Z, THREADS, SMEM_BYTES>>>(x1, x2, out, n);
}